// round 13
// baseline (speedup 1.0000x reference)
#include <cuda_runtime.h>
#include <cuda_bf16.h>
#include <cstddef>

// ---------------------------------------------------------------------------
// MS-SSIM, 32x1x512x512 fp32 pairs, 5 levels, 11x11 Gaussian (sigma=1.5).
// SINGLE launch, interleaved scheduling:
//   gb < 10240 : gb%5==0 -> pyramid block (2048), else level-0 SSIM (8192)
//   10240..12287 : level-1 SSIM (waits pyr1_done)
//   12288..12959 : level-2..4 SSIM (waits pyr_done)
//   12960        : finisher (computes output, resets state for graph replay)
// (s,d) = (u+v, u-v) basis, packed f32x2, conflict-free + balanced h-pass.
// Level-0 body constant-propagated (compile-time H=512).
// ---------------------------------------------------------------------------

#define TILE  32
#define HALO  5
#define SROWS (TILE + 2*HALO)   // 42
#define SSTR  43
#define HSTR  33
#define WIN   11

typedef unsigned long long u64;

#define GW0 0.00102839f
#define GW1 0.00759870f
#define GW2 0.03600080f
#define GW3 0.10936070f
#define GW4 0.21300540f
#define GW5 0.26601170f

#define C1F 1.0e-4f
#define C2F 9.0e-4f

#define OFF1 ((size_t)0)
#define OFF2 (OFF1 + (size_t)32 * 256 * 256)
#define OFF3 (OFF2 + (size_t)32 * 128 * 128)
#define OFF4 (OFF3 + (size_t)32 * 64 * 64)

#define N_PYR   2048
#define N_SSIM  10912
#define B_L1    10240
#define B_L2    12288
#define B_L3    12800
#define B_L4    12928
#define B_FIN   12960

__device__ float  g_buf1[32u * 87040u];
__device__ float  g_buf2[32u * 87040u];
__device__ double g_sums[10];
__device__ int    g_pyr1_done;
__device__ int    g_pyr_done;
__device__ int    g_done;

// ---- f32x2 packed helpers -------------------------------------------------
__device__ __forceinline__ void fma2(u64& d, u64 a, u64 b) {
    asm("fma.rn.f32x2 %0, %1, %2, %0;" : "+l"(d) : "l"(a), "l"(b));
}
__device__ __forceinline__ u64 mul2(u64 a, u64 b) {
    u64 r;
    asm("mul.rn.f32x2 %0, %1, %2;" : "=l"(r) : "l"(a), "l"(b));
    return r;
}
__device__ __forceinline__ u64 pack2(float x, float y) {
    u64 r;
    asm("mov.b64 %0, {%1, %2};" : "=l"(r) : "f"(x), "f"(y));
    return r;
}
__device__ __forceinline__ float lo32(u64 a) {
    float r;
    asm("{ .reg .f32 hi; mov.b64 {%0, hi}, %1; }" : "=f"(r) : "l"(a));
    return r;
}
__device__ __forceinline__ float hi32(u64 a) {
    float r;
    asm("{ .reg .f32 lo; mov.b64 {lo, %0}, %1; }" : "=f"(r) : "l"(a));
    return r;
}

struct SsimSmem {
    u64   sSD[SROWS][SSTR];
    u64   hbSD[SROWS][HSTR];
    u64   hbPQ[SROWS][HSTR];
    float wsum[8][2];
};
struct PyrSmem {
    float a1[32][33], a2[32][33];
    float e1[16][17], e2[16][17];
    float c1[8][9],  c2[8][9];
};

// weight selector on compile-time k (0..10), using symmetric immediates
__device__ __forceinline__ u64 wsel(int k) {
    const int kk = (k <= 5) ? k : (10 - k);
    switch (kk) {
        case 0:  return pack2(GW0, GW0);
        case 1:  return pack2(GW1, GW1);
        case 2:  return pack2(GW2, GW2);
        case 3:  return pack2(GW3, GW3);
        case 4:  return pack2(GW4, GW4);
        default: return pack2(GW5, GW5);
    }
}

// ---------------------------------------------------------------------------
// SSIM tile body. Called with literal level/H for level 0 (constant-folds),
// runtime values for levels 1..4.
// ---------------------------------------------------------------------------
__device__ __forceinline__ void ssim_body(
    int level, int H, int shift, int idx,
    const float* __restrict__ p1base, const float* __restrict__ p2base,
    SsimSmem& S, double* __restrict__ sums, int* __restrict__ done,
    int tx, int ty, int tid)
{
    const int nbx = 1 << shift;
    const int b   = idx >> (2 * shift);
    const int rem = idx & ((1 << (2 * shift)) - 1);
    const int byi = rem >> shift;
    const int bxi = rem & (nbx - 1);

    const int x0 = bxi * TILE - HALO;
    const int y0 = byi * TILE - HALO;

    const float* __restrict__ p1 = p1base + (size_t)b * H * H;
    const float* __restrict__ p2 = p2base + (size_t)b * H * H;

    // ---- load 42x42 halo tile as packed (u+v, u-v); zero pad = SAME ----
    const bool interior = (x0 >= 0) && (y0 >= 0) &&
                          (x0 + SROWS <= H) && (y0 + SROWS <= H);
    if (interior) {
#pragma unroll
        for (int rr = 0; rr < 6; rr++) {
            const int r = ty + 8 * rr;
            if (r < SROWS) {
                const size_t row = (size_t)(y0 + r) * H + x0;
#pragma unroll
                for (int cc = 0; cc < 2; cc++) {
                    const int c = tx + 32 * cc;
                    if (c < SROWS) {
                        const float u = p1[row + c];
                        const float v = p2[row + c];
                        S.sSD[r][c] = pack2(u + v, u - v);
                    }
                }
            }
        }
    } else {
#pragma unroll
        for (int rr = 0; rr < 6; rr++) {
            const int r = ty + 8 * rr;
            if (r < SROWS) {
                const int gy = y0 + r;
                const bool yok = (gy >= 0) && (gy < H);
#pragma unroll
                for (int cc = 0; cc < 2; cc++) {
                    const int c = tx + 32 * cc;
                    if (c < SROWS) {
                        const int gx = x0 + c;
                        float u = 0.f, v = 0.f;
                        if (yok && gx >= 0 && gx < H) {
                            u = p1[(size_t)gy * H + gx];
                            v = p2[(size_t)gy * H + gx];
                        }
                        S.sSD[r][c] = pack2(u + v, u - v);
                    }
                }
            }
        }
    }
    __syncthreads();

    // ---- horizontal pass, balanced + conflict-free ----
    {
        const int cg4  = tid & 3;
        const int rr   = tid >> 2;
        const int half = (rr >= 32) ? 1 : 0;
        const int r    = rr - (half << 5);
        const int cg   = (cg4 + (half << 2)) << 2;
        const u64* __restrict__ srow = &S.sSD[r][cg];

        u64 ASD[4] = {0ull, 0ull, 0ull, 0ull};
        u64 APQ[4] = {0ull, 0ull, 0ull, 0ull};
#pragma unroll
        for (int i = 0; i < 14; i++) {
            const u64 sd = srow[i];
            const u64 sq = mul2(sd, sd);
#pragma unroll
            for (int j = 0; j < 4; j++) {
                const int k = i - j;
                if (k >= 0 && k < WIN) {
                    fma2(ASD[j], wsel(k), sd);
                    fma2(APQ[j], wsel(k), sq);
                }
            }
        }
#pragma unroll
        for (int j = 0; j < 4; j++) {
            S.hbSD[r][cg + j] = ASD[j];
            S.hbPQ[r][cg + j] = APQ[j];
        }
    }
    // tail rows 32..41: 160 two-output subtasks
    if (tid < 160) {
        const int G  = tid >> 4;
        const int L  = tid & 15;
        const int rp = G % 5;
        const int ch = G / 5;
        const int r  = 32 + 2 * rp + (L >> 3);
        const int sub = (L & 7) + 8 * ch;
        const int c0 = sub << 1;
        const u64* __restrict__ srow = &S.sSD[r][c0];

        u64 A0SD = 0ull, A0PQ = 0ull, A1SD = 0ull, A1PQ = 0ull;
#pragma unroll
        for (int i = 0; i < 12; i++) {
            const u64 sd = srow[i];
            const u64 sq = mul2(sd, sd);
            if (i < 11) {
                fma2(A0SD, wsel(i), sd);
                fma2(A0PQ, wsel(i), sq);
            }
            if (i >= 1) {
                fma2(A1SD, wsel(i - 1), sd);
                fma2(A1PQ, wsel(i - 1), sq);
            }
        }
        S.hbSD[r][c0]     = A0SD;
        S.hbPQ[r][c0]     = A0PQ;
        S.hbSD[r][c0 + 1] = A1SD;
        S.hbPQ[r][c0 + 1] = A1PQ;
    }
    __syncthreads();

    // ---- vertical pass: thread = col tx, rows 4*ty .. 4*ty+3 ----
    u64 VSD[4] = {0ull, 0ull, 0ull, 0ull};
    u64 VPQ[4] = {0ull, 0ull, 0ull, 0ull};

    const int r0 = ty << 2;
#pragma unroll
    for (int i = 0; i < 14; i++) {
        const u64 hSD = S.hbSD[r0 + i][tx];
        const u64 hPQ = S.hbPQ[r0 + i][tx];
#pragma unroll
        for (int j = 0; j < 4; j++) {
            const int k = i - j;
            if (k >= 0 && k < WIN) {
                fma2(VSD[j], wsel(k), hSD);
                fma2(VPQ[j], wsel(k), hPQ);
            }
        }
    }

    float lssim = 0.f, lmcs = 0.f;
#pragma unroll
    for (int j = 0; j < 4; j++) {
        const float ms = lo32(VSD[j]);
        const float md = hi32(VSD[j]);
        const float P  = lo32(VPQ[j]);
        const float Q  = hi32(VPQ[j]);
        const float S2 = ms * ms;
        const float D2 = md * md;
        const float a  = 0.5f * (S2 - D2);
        const float bb = 0.5f * (S2 + D2);
        const float num2 = 0.5f * (P - Q) - a + C2F;
        const float den2 = 0.5f * (P + Q) - bb + C2F;
        const float mcs  = __fdividef(num2, den2);
        const float ssim = __fdividef(a + C1F, bb + C1F) * mcs;
        lssim += ssim;
        lmcs  += mcs;
    }

#pragma unroll
    for (int o = 16; o > 0; o >>= 1) {
        lssim += __shfl_down_sync(0xffffffffu, lssim, o);
        lmcs  += __shfl_down_sync(0xffffffffu, lmcs,  o);
    }
    if (tx == 0) {
        S.wsum[ty][0] = lssim;
        S.wsum[ty][1] = lmcs;
    }
    __syncthreads();
    if (ty == 0 && tx < 8) {
        float a = S.wsum[tx][0];
        float c = S.wsum[tx][1];
#pragma unroll
        for (int o = 4; o > 0; o >>= 1) {
            a += __shfl_down_sync(0xffu, a, o);
            c += __shfl_down_sync(0xffu, c, o);
        }
        if (tx == 0) {
            atomicAdd(&sums[2 * level + 0], (double)a);
            atomicAdd(&sums[2 * level + 1], (double)c);
            __threadfence();
            atomicAdd(done, 1);
        }
    }
}

// ---------------------------------------------------------------------------
__global__ __launch_bounds__(256, 6)
void mega_kernel(const float* __restrict__ img1,
                 const float* __restrict__ img2,
                 float* __restrict__ buf1,
                 float* __restrict__ buf2,
                 double* __restrict__ sums,
                 int* __restrict__ pyr1_done,
                 int* __restrict__ pyr_done,
                 int* __restrict__ done,
                 float* __restrict__ out)
{
    __shared__ __align__(16) unsigned char smraw[sizeof(SsimSmem)];

    const int tx  = threadIdx.x;
    const int ty  = threadIdx.y;
    const int tid = ty * 32 + tx;
    const int gb  = blockIdx.x;

    // ======================= finisher block ================================
    if (gb == B_FIN) {
        if (tid == 0) {
            volatile int* f = done;
            while (*f < N_SSIM) __nanosleep(256);
            __threadfence();

            const float w[5] = {0.0448f, 0.2856f, 0.3001f, 0.2363f, 0.1333f};
            float acc = 0.f;
#pragma unroll
            for (int l = 0; l < 4; l++) {
                const float N = 32.f * (float)(512 >> l) * (float)(512 >> l);
                const float mcs = (float)(sums[2 * l + 1] / (double)N);
                acc += w[l] * __log2f(mcs);
            }
            {
                const float N = 32.f * 32.f * 32.f;
                const float ssim = (float)(sums[2 * 4 + 0] / (double)N);
                acc += w[4] * __log2f(ssim);
            }
            out[0] = exp2f(acc);

#pragma unroll
            for (int i = 0; i < 10; i++) sums[i] = 0.0;
            __threadfence();
            *pyr1_done = 0;
            *pyr_done  = 0;
            *done      = 0;
        }
        return;
    }

    // ============ interleaved zone: pyramid (1/5) + level-0 (4/5) ==========
    if (gb < B_L1) {
        const int q  = gb / 5;
        const int rm = gb - 5 * q;

        if (rm == 0) {
            // ------------------- pyramid block (index q) -------------------
            PyrSmem& P = *reinterpret_cast<PyrSmem*>(smraw);
            const int bx = q & 7, by = (q >> 3) & 7, b = q >> 6;

            const float* __restrict__ p1 = img1 + (size_t)b * 512 * 512;
            const float* __restrict__ p2 = img2 + (size_t)b * 512 * 512;

#pragma unroll
            for (int it = 0; it < 4; it++) {
                const int o  = tid + 256 * it;
                const int oy = o >> 5, ox = o & 31;
                const size_t r0 = (size_t)(by * 64 + 2 * oy) * 512 + bx * 64 + 2 * ox;
                const float2 u0 = *(const float2*)(p1 + r0);
                const float2 u1 = *(const float2*)(p1 + r0 + 512);
                const float2 v0 = *(const float2*)(p2 + r0);
                const float2 v1 = *(const float2*)(p2 + r0 + 512);
                const float d1 = 0.25f * (u0.x + u0.y + u1.x + u1.y);
                const float d2 = 0.25f * (v0.x + v0.y + v1.x + v1.y);
                P.a1[oy][ox] = d1;
                P.a2[oy][ox] = d2;
                const size_t gi = ((size_t)b * 256 + (by * 32 + oy)) * 256 + (bx * 32 + ox);
                buf1[OFF1 + gi] = d1;
                buf2[OFF1 + gi] = d2;
            }
            __threadfence();
            __syncthreads();
            if (tid == 0) atomicAdd(pyr1_done, 1);

            {
                const int oy = tid >> 4, ox = tid & 15;
                const float d1 = 0.25f * (P.a1[2*oy][2*ox] + P.a1[2*oy][2*ox+1] +
                                          P.a1[2*oy+1][2*ox] + P.a1[2*oy+1][2*ox+1]);
                const float d2 = 0.25f * (P.a2[2*oy][2*ox] + P.a2[2*oy][2*ox+1] +
                                          P.a2[2*oy+1][2*ox] + P.a2[2*oy+1][2*ox+1]);
                P.e1[oy][ox] = d1;
                P.e2[oy][ox] = d2;
                const size_t gi = ((size_t)b * 128 + (by * 16 + oy)) * 128 + (bx * 16 + ox);
                buf1[OFF2 + gi] = d1;
                buf2[OFF2 + gi] = d2;
            }
            __syncthreads();

            if (tid < 64) {
                const int oy = tid >> 3, ox = tid & 7;
                const float d1 = 0.25f * (P.e1[2*oy][2*ox] + P.e1[2*oy][2*ox+1] +
                                          P.e1[2*oy+1][2*ox] + P.e1[2*oy+1][2*ox+1]);
                const float d2 = 0.25f * (P.e2[2*oy][2*ox] + P.e2[2*oy][2*ox+1] +
                                          P.e2[2*oy+1][2*ox] + P.e2[2*oy+1][2*ox+1]);
                P.c1[oy][ox] = d1;
                P.c2[oy][ox] = d2;
                const size_t gi = ((size_t)b * 64 + (by * 8 + oy)) * 64 + (bx * 8 + ox);
                buf1[OFF3 + gi] = d1;
                buf2[OFF3 + gi] = d2;
            }
            __syncthreads();

            if (tid < 16) {
                const int oy = tid >> 2, ox = tid & 3;
                const float d1 = 0.25f * (P.c1[2*oy][2*ox] + P.c1[2*oy][2*ox+1] +
                                          P.c1[2*oy+1][2*ox] + P.c1[2*oy+1][2*ox+1]);
                const float d2 = 0.25f * (P.c2[2*oy][2*ox] + P.c2[2*oy][2*ox+1] +
                                          P.c2[2*oy+1][2*ox] + P.c2[2*oy+1][2*ox+1]);
                const size_t gi = ((size_t)b * 32 + (by * 4 + oy)) * 32 + (bx * 4 + ox);
                buf1[OFF4 + gi] = d1;
                buf2[OFF4 + gi] = d2;
            }
            __threadfence();
            __syncthreads();
            if (tid == 0) atomicAdd(pyr_done, 1);
            return;
        }

        // ------------------- level-0 ssim block -------------------
        SsimSmem& S = *reinterpret_cast<SsimSmem*>(smraw);
        const int idx = q * 4 + (rm - 1);     // 0..8191
        // literal args -> constant-propagated body (H=512 compile-time)
        ssim_body(0, 512, 4, idx, img1, img2, S, sums, done, tx, ty, tid);
        return;
    }

    // ======================= levels 1..4 ===================================
    SsimSmem& S = *reinterpret_cast<SsimSmem*>(smraw);

    int level, start;
    const float *p1base, *p2base;
    if (gb < B_L2)      { level = 1; start = B_L1; p1base = buf1 + OFF1; p2base = buf2 + OFF1; }
    else if (gb < B_L3) { level = 2; start = B_L2; p1base = buf1 + OFF2; p2base = buf2 + OFF2; }
    else if (gb < B_L4) { level = 3; start = B_L3; p1base = buf1 + OFF3; p2base = buf2 + OFF3; }
    else                { level = 4; start = B_L4; p1base = buf1 + OFF4; p2base = buf2 + OFF4; }

    if (level == 1) {
        if (tid == 0) {
            volatile int* f = pyr1_done;
            while (*f < N_PYR) __nanosleep(128);
            __threadfence();
        }
        __syncthreads();
    } else {
        if (tid == 0) {
            volatile int* f = pyr_done;
            while (*f < N_PYR) __nanosleep(128);
            __threadfence();
        }
        __syncthreads();
    }

    const int shift = 4 - level;
    const int H     = 512 >> level;
    const int idx   = gb - start;
    ssim_body(level, H, shift, idx, p1base, p2base, S, sums, done, tx, ty, tid);
}

extern "C" void kernel_launch(void* const* d_in, const int* in_sizes, int n_in,
                              void* d_out, int out_size)
{
    const float* img1 = (const float*)d_in[0];
    const float* img2 = (const float*)d_in[1];
    float* out = (float*)d_out;

    double* sums = nullptr;
    float*  buf1 = nullptr;
    float*  buf2 = nullptr;
    int *f1 = nullptr, *f2 = nullptr, *f3 = nullptr;
    cudaGetSymbolAddress((void**)&sums, g_sums);
    cudaGetSymbolAddress((void**)&buf1, g_buf1);
    cudaGetSymbolAddress((void**)&buf2, g_buf2);
    cudaGetSymbolAddress((void**)&f1, g_pyr1_done);
    cudaGetSymbolAddress((void**)&f2, g_pyr_done);
    cudaGetSymbolAddress((void**)&f3, g_done);

    mega_kernel<<<B_FIN + 1, dim3(32, 8)>>>(img1, img2, buf1, buf2,
                                            sums, f1, f2, f3, out);
}

// round 14
// speedup vs baseline: 1.0468x; 1.0468x over previous
#include <cuda_runtime.h>
#include <cuda_bf16.h>
#include <cstddef>

// ---------------------------------------------------------------------------
// MS-SSIM, 32x1x512x512 fp32 pairs, 5 levels, 11x11 Gaussian (sigma=1.5).
// SINGLE launch, interleaved scheduling (pyramid 1/5 of first 10240 blocks),
// (s,d) basis, packed f32x2. Round 14: hbPQ aliased over sSD (PQ accumulators
// carried in registers across an extra barrier) -> smem 25.7KB -> 7 blocks/SM.
// ---------------------------------------------------------------------------

#define TILE  32
#define HALO  5
#define SROWS (TILE + 2*HALO)   // 42
#define SSTR  43
#define HSTR  33
#define WIN   11

typedef unsigned long long u64;

#define GW0 0.00102839f
#define GW1 0.00759870f
#define GW2 0.03600080f
#define GW3 0.10936070f
#define GW4 0.21300540f
#define GW5 0.26601170f

#define C1F 1.0e-4f
#define C2F 9.0e-4f

#define OFF1 ((size_t)0)
#define OFF2 (OFF1 + (size_t)32 * 256 * 256)
#define OFF3 (OFF2 + (size_t)32 * 128 * 128)
#define OFF4 (OFF3 + (size_t)32 * 64 * 64)

#define N_PYR   2048
#define N_SSIM  10912
#define B_L1    10240
#define B_L2    12288
#define B_L3    12800
#define B_L4    12928
#define B_FIN   12960

__device__ float  g_buf1[32u * 87040u];
__device__ float  g_buf2[32u * 87040u];
__device__ double g_sums[10];
__device__ int    g_pyr1_done;
__device__ int    g_pyr_done;
__device__ int    g_done;

// ---- f32x2 packed helpers -------------------------------------------------
__device__ __forceinline__ void fma2(u64& d, u64 a, u64 b) {
    asm("fma.rn.f32x2 %0, %1, %2, %0;" : "+l"(d) : "l"(a), "l"(b));
}
__device__ __forceinline__ u64 mul2(u64 a, u64 b) {
    u64 r;
    asm("mul.rn.f32x2 %0, %1, %2;" : "=l"(r) : "l"(a), "l"(b));
    return r;
}
__device__ __forceinline__ u64 pack2(float x, float y) {
    u64 r;
    asm("mov.b64 %0, {%1, %2};" : "=l"(r) : "f"(x), "f"(y));
    return r;
}
__device__ __forceinline__ float lo32(u64 a) {
    float r;
    asm("{ .reg .f32 hi; mov.b64 {%0, hi}, %1; }" : "=f"(r) : "l"(a));
    return r;
}
__device__ __forceinline__ float hi32(u64 a) {
    float r;
    asm("{ .reg .f32 lo; mov.b64 {lo, %0}, %1; }" : "=f"(r) : "l"(a));
    return r;
}

// hbPQ aliases the sSD region (sSD is dead after the h-pass reads).
struct SsimSmem {
    union {
        u64 sSD[SROWS][SSTR];      // 14.4 KB
        u64 hbPQ[SROWS][HSTR];     // 11.1 KB (fits inside)
    };
    u64   hbSD[SROWS][HSTR];       // 11.1 KB
    float wsum[8][2];
};
struct PyrSmem {
    float a1[32][33], a2[32][33];
    float e1[16][17], e2[16][17];
    float c1[8][9],  c2[8][9];
};

__device__ __forceinline__ u64 wsel(int k) {
    const int kk = (k <= 5) ? k : (10 - k);
    switch (kk) {
        case 0:  return pack2(GW0, GW0);
        case 1:  return pack2(GW1, GW1);
        case 2:  return pack2(GW2, GW2);
        case 3:  return pack2(GW3, GW3);
        case 4:  return pack2(GW4, GW4);
        default: return pack2(GW5, GW5);
    }
}

// ---------------------------------------------------------------------------
__device__ __forceinline__ void ssim_body(
    int level, int H, int shift, int idx,
    const float* __restrict__ p1base, const float* __restrict__ p2base,
    SsimSmem& S, double* __restrict__ sums, int* __restrict__ done,
    int tx, int ty, int tid)
{
    const int nbx = 1 << shift;
    const int b   = idx >> (2 * shift);
    const int rem = idx & ((1 << (2 * shift)) - 1);
    const int byi = rem >> shift;
    const int bxi = rem & (nbx - 1);

    const int x0 = bxi * TILE - HALO;
    const int y0 = byi * TILE - HALO;

    const float* __restrict__ p1 = p1base + (size_t)b * H * H;
    const float* __restrict__ p2 = p2base + (size_t)b * H * H;

    // ---- load 42x42 halo tile as packed (u+v, u-v); zero pad = SAME ----
    const bool interior = (x0 >= 0) && (y0 >= 0) &&
                          (x0 + SROWS <= H) && (y0 + SROWS <= H);
    if (interior) {
#pragma unroll
        for (int rr = 0; rr < 6; rr++) {
            const int r = ty + 8 * rr;
            if (r < SROWS) {
                const size_t row = (size_t)(y0 + r) * H + x0;
#pragma unroll
                for (int cc = 0; cc < 2; cc++) {
                    const int c = tx + 32 * cc;
                    if (c < SROWS) {
                        const float u = p1[row + c];
                        const float v = p2[row + c];
                        S.sSD[r][c] = pack2(u + v, u - v);
                    }
                }
            }
        }
    } else {
#pragma unroll
        for (int rr = 0; rr < 6; rr++) {
            const int r = ty + 8 * rr;
            if (r < SROWS) {
                const int gy = y0 + r;
                const bool yok = (gy >= 0) && (gy < H);
#pragma unroll
                for (int cc = 0; cc < 2; cc++) {
                    const int c = tx + 32 * cc;
                    if (c < SROWS) {
                        const int gx = x0 + c;
                        float u = 0.f, v = 0.f;
                        if (yok && gx >= 0 && gx < H) {
                            u = p1[(size_t)gy * H + gx];
                            v = p2[(size_t)gy * H + gx];
                        }
                        S.sSD[r][c] = pack2(u + v, u - v);
                    }
                }
            }
        }
    }
    __syncthreads();

    // ---- horizontal pass (reads sSD, writes hbSD now, PQ kept in regs) ----
    u64 APQ[4];
    int mr, mcg;                 // main task coords
    {
        const int cg4  = tid & 3;
        const int rr   = tid >> 2;
        const int half = (rr >= 32) ? 1 : 0;
        mr  = rr - (half << 5);
        mcg = (cg4 + (half << 2)) << 2;
        const u64* __restrict__ srow = &S.sSD[mr][mcg];

        u64 ASD[4] = {0ull, 0ull, 0ull, 0ull};
        APQ[0] = APQ[1] = APQ[2] = APQ[3] = 0ull;
#pragma unroll
        for (int i = 0; i < 14; i++) {
            const u64 sd = srow[i];
            const u64 sq = mul2(sd, sd);
#pragma unroll
            for (int j = 0; j < 4; j++) {
                const int k = i - j;
                if (k >= 0 && k < WIN) {
                    fma2(ASD[j], wsel(k), sd);
                    fma2(APQ[j], wsel(k), sq);
                }
            }
        }
#pragma unroll
        for (int j = 0; j < 4; j++)
            S.hbSD[mr][mcg + j] = ASD[j];
    }
    // tail rows 32..41: 160 two-output subtasks; PQ kept in regs
    u64 T0PQ = 0ull, T1PQ = 0ull;
    int trr = 0, tc0 = 0;
    if (tid < 160) {
        const int G  = tid >> 4;
        const int L  = tid & 15;
        const int rp = G % 5;
        const int ch = G / 5;
        trr = 32 + 2 * rp + (L >> 3);
        const int sub = (L & 7) + 8 * ch;
        tc0 = sub << 1;
        const u64* __restrict__ srow = &S.sSD[trr][tc0];

        u64 A0SD = 0ull, A1SD = 0ull;
#pragma unroll
        for (int i = 0; i < 12; i++) {
            const u64 sd = srow[i];
            const u64 sq = mul2(sd, sd);
            if (i < 11) {
                fma2(A0SD, wsel(i), sd);
                fma2(T0PQ, wsel(i), sq);
            }
            if (i >= 1) {
                fma2(A1SD, wsel(i - 1), sd);
                fma2(T1PQ, wsel(i - 1), sq);
            }
        }
        S.hbSD[trr][tc0]     = A0SD;
        S.hbSD[trr][tc0 + 1] = A1SD;
    }
    __syncthreads();   // all sSD reads complete -> safe to overwrite alias

    // ---- write PQ into the alias region ----
#pragma unroll
    for (int j = 0; j < 4; j++)
        S.hbPQ[mr][mcg + j] = APQ[j];
    if (tid < 160) {
        S.hbPQ[trr][tc0]     = T0PQ;
        S.hbPQ[trr][tc0 + 1] = T1PQ;
    }
    __syncthreads();

    // ---- vertical pass: thread = col tx, rows 4*ty .. 4*ty+3 ----
    u64 VSD[4] = {0ull, 0ull, 0ull, 0ull};
    u64 VPQ[4] = {0ull, 0ull, 0ull, 0ull};

    const int r0 = ty << 2;
#pragma unroll
    for (int i = 0; i < 14; i++) {
        const u64 hSD = S.hbSD[r0 + i][tx];
        const u64 hPQ = S.hbPQ[r0 + i][tx];
#pragma unroll
        for (int j = 0; j < 4; j++) {
            const int k = i - j;
            if (k >= 0 && k < WIN) {
                fma2(VSD[j], wsel(k), hSD);
                fma2(VPQ[j], wsel(k), hPQ);
            }
        }
    }

    float lssim = 0.f, lmcs = 0.f;
#pragma unroll
    for (int j = 0; j < 4; j++) {
        const float ms = lo32(VSD[j]);
        const float md = hi32(VSD[j]);
        const float P  = lo32(VPQ[j]);
        const float Q  = hi32(VPQ[j]);
        const float S2 = ms * ms;
        const float D2 = md * md;
        const float a  = 0.5f * (S2 - D2);
        const float bb = 0.5f * (S2 + D2);
        const float num2 = 0.5f * (P - Q) - a + C2F;
        const float den2 = 0.5f * (P + Q) - bb + C2F;
        const float mcs  = __fdividef(num2, den2);
        const float ssim = __fdividef(a + C1F, bb + C1F) * mcs;
        lssim += ssim;
        lmcs  += mcs;
    }

#pragma unroll
    for (int o = 16; o > 0; o >>= 1) {
        lssim += __shfl_down_sync(0xffffffffu, lssim, o);
        lmcs  += __shfl_down_sync(0xffffffffu, lmcs,  o);
    }
    if (tx == 0) {
        S.wsum[ty][0] = lssim;
        S.wsum[ty][1] = lmcs;
    }
    __syncthreads();
    if (ty == 0 && tx < 8) {
        float a = S.wsum[tx][0];
        float c = S.wsum[tx][1];
#pragma unroll
        for (int o = 4; o > 0; o >>= 1) {
            a += __shfl_down_sync(0xffu, a, o);
            c += __shfl_down_sync(0xffu, c, o);
        }
        if (tx == 0) {
            atomicAdd(&sums[2 * level + 0], (double)a);
            atomicAdd(&sums[2 * level + 1], (double)c);
            __threadfence();
            atomicAdd(done, 1);
        }
    }
}

// ---------------------------------------------------------------------------
__global__ __launch_bounds__(256, 7)
void mega_kernel(const float* __restrict__ img1,
                 const float* __restrict__ img2,
                 float* __restrict__ buf1,
                 float* __restrict__ buf2,
                 double* __restrict__ sums,
                 int* __restrict__ pyr1_done,
                 int* __restrict__ pyr_done,
                 int* __restrict__ done,
                 float* __restrict__ out)
{
    __shared__ __align__(16) unsigned char smraw[sizeof(SsimSmem)];

    const int tx  = threadIdx.x;
    const int ty  = threadIdx.y;
    const int tid = ty * 32 + tx;
    const int gb  = blockIdx.x;

    // ======================= finisher block ================================
    if (gb == B_FIN) {
        if (tid == 0) {
            volatile int* f = done;
            while (*f < N_SSIM) __nanosleep(256);
            __threadfence();

            const float w[5] = {0.0448f, 0.2856f, 0.3001f, 0.2363f, 0.1333f};
            float acc = 0.f;
#pragma unroll
            for (int l = 0; l < 4; l++) {
                const float N = 32.f * (float)(512 >> l) * (float)(512 >> l);
                const float mcs = (float)(sums[2 * l + 1] / (double)N);
                acc += w[l] * __log2f(mcs);
            }
            {
                const float N = 32.f * 32.f * 32.f;
                const float ssim = (float)(sums[2 * 4 + 0] / (double)N);
                acc += w[4] * __log2f(ssim);
            }
            out[0] = exp2f(acc);

#pragma unroll
            for (int i = 0; i < 10; i++) sums[i] = 0.0;
            __threadfence();
            *pyr1_done = 0;
            *pyr_done  = 0;
            *done      = 0;
        }
        return;
    }

    // ============ interleaved zone: pyramid (1/5) + level-0 (4/5) ==========
    if (gb < B_L1) {
        const int q  = gb / 5;
        const int rm = gb - 5 * q;

        if (rm == 0) {
            PyrSmem& P = *reinterpret_cast<PyrSmem*>(smraw);
            const int bx = q & 7, by = (q >> 3) & 7, b = q >> 6;

            const float* __restrict__ p1 = img1 + (size_t)b * 512 * 512;
            const float* __restrict__ p2 = img2 + (size_t)b * 512 * 512;

#pragma unroll
            for (int it = 0; it < 4; it++) {
                const int o  = tid + 256 * it;
                const int oy = o >> 5, ox = o & 31;
                const size_t r0 = (size_t)(by * 64 + 2 * oy) * 512 + bx * 64 + 2 * ox;
                const float2 u0 = *(const float2*)(p1 + r0);
                const float2 u1 = *(const float2*)(p1 + r0 + 512);
                const float2 v0 = *(const float2*)(p2 + r0);
                const float2 v1 = *(const float2*)(p2 + r0 + 512);
                const float d1 = 0.25f * (u0.x + u0.y + u1.x + u1.y);
                const float d2 = 0.25f * (v0.x + v0.y + v1.x + v1.y);
                P.a1[oy][ox] = d1;
                P.a2[oy][ox] = d2;
                const size_t gi = ((size_t)b * 256 + (by * 32 + oy)) * 256 + (bx * 32 + ox);
                buf1[OFF1 + gi] = d1;
                buf2[OFF1 + gi] = d2;
            }
            __threadfence();
            __syncthreads();
            if (tid == 0) atomicAdd(pyr1_done, 1);

            {
                const int oy = tid >> 4, ox = tid & 15;
                const float d1 = 0.25f * (P.a1[2*oy][2*ox] + P.a1[2*oy][2*ox+1] +
                                          P.a1[2*oy+1][2*ox] + P.a1[2*oy+1][2*ox+1]);
                const float d2 = 0.25f * (P.a2[2*oy][2*ox] + P.a2[2*oy][2*ox+1] +
                                          P.a2[2*oy+1][2*ox] + P.a2[2*oy+1][2*ox+1]);
                P.e1[oy][ox] = d1;
                P.e2[oy][ox] = d2;
                const size_t gi = ((size_t)b * 128 + (by * 16 + oy)) * 128 + (bx * 16 + ox);
                buf1[OFF2 + gi] = d1;
                buf2[OFF2 + gi] = d2;
            }
            __syncthreads();

            if (tid < 64) {
                const int oy = tid >> 3, ox = tid & 7;
                const float d1 = 0.25f * (P.e1[2*oy][2*ox] + P.e1[2*oy][2*ox+1] +
                                          P.e1[2*oy+1][2*ox] + P.e1[2*oy+1][2*ox+1]);
                const float d2 = 0.25f * (P.e2[2*oy][2*ox] + P.e2[2*oy][2*ox+1] +
                                          P.e2[2*oy+1][2*ox] + P.e2[2*oy+1][2*ox+1]);
                P.c1[oy][ox] = d1;
                P.c2[oy][ox] = d2;
                const size_t gi = ((size_t)b * 64 + (by * 8 + oy)) * 64 + (bx * 8 + ox);
                buf1[OFF3 + gi] = d1;
                buf2[OFF3 + gi] = d2;
            }
            __syncthreads();

            if (tid < 16) {
                const int oy = tid >> 2, ox = tid & 3;
                const float d1 = 0.25f * (P.c1[2*oy][2*ox] + P.c1[2*oy][2*ox+1] +
                                          P.c1[2*oy+1][2*ox] + P.c1[2*oy+1][2*ox+1]);
                const float d2 = 0.25f * (P.c2[2*oy][2*ox] + P.c2[2*oy][2*ox+1] +
                                          P.c2[2*oy+1][2*ox] + P.c2[2*oy+1][2*ox+1]);
                const size_t gi = ((size_t)b * 32 + (by * 4 + oy)) * 32 + (bx * 4 + ox);
                buf1[OFF4 + gi] = d1;
                buf2[OFF4 + gi] = d2;
            }
            __threadfence();
            __syncthreads();
            if (tid == 0) atomicAdd(pyr_done, 1);
            return;
        }

        SsimSmem& S = *reinterpret_cast<SsimSmem*>(smraw);
        const int idx = q * 4 + (rm - 1);
        ssim_body(0, 512, 4, idx, img1, img2, S, sums, done, tx, ty, tid);
        return;
    }

    // ======================= levels 1..4 ===================================
    SsimSmem& S = *reinterpret_cast<SsimSmem*>(smraw);

    int level, start;
    const float *p1base, *p2base;
    if (gb < B_L2)      { level = 1; start = B_L1; p1base = buf1 + OFF1; p2base = buf2 + OFF1; }
    else if (gb < B_L3) { level = 2; start = B_L2; p1base = buf1 + OFF2; p2base = buf2 + OFF2; }
    else if (gb < B_L4) { level = 3; start = B_L3; p1base = buf1 + OFF3; p2base = buf2 + OFF3; }
    else                { level = 4; start = B_L4; p1base = buf1 + OFF4; p2base = buf2 + OFF4; }

    if (level == 1) {
        if (tid == 0) {
            volatile int* f = pyr1_done;
            while (*f < N_PYR) __nanosleep(128);
            __threadfence();
        }
        __syncthreads();
    } else {
        if (tid == 0) {
            volatile int* f = pyr_done;
            while (*f < N_PYR) __nanosleep(128);
            __threadfence();
        }
        __syncthreads();
    }

    const int shift = 4 - level;
    const int H     = 512 >> level;
    const int idx   = gb - start;
    ssim_body(level, H, shift, idx, p1base, p2base, S, sums, done, tx, ty, tid);
}

extern "C" void kernel_launch(void* const* d_in, const int* in_sizes, int n_in,
                              void* d_out, int out_size)
{
    const float* img1 = (const float*)d_in[0];
    const float* img2 = (const float*)d_in[1];
    float* out = (float*)d_out;

    double* sums = nullptr;
    float*  buf1 = nullptr;
    float*  buf2 = nullptr;
    int *f1 = nullptr, *f2 = nullptr, *f3 = nullptr;
    cudaGetSymbolAddress((void**)&sums, g_sums);
    cudaGetSymbolAddress((void**)&buf1, g_buf1);
    cudaGetSymbolAddress((void**)&buf2, g_buf2);
    cudaGetSymbolAddress((void**)&f1, g_pyr1_done);
    cudaGetSymbolAddress((void**)&f2, g_pyr_done);
    cudaGetSymbolAddress((void**)&f3, g_done);

    mega_kernel<<<B_FIN + 1, dim3(32, 8)>>>(img1, img2, buf1, buf2,
                                            sums, f1, f2, f3, out);
}

// round 15
// speedup vs baseline: 1.0706x; 1.0227x over previous
#include <cuda_runtime.h>
#include <cuda_bf16.h>
#include <cstddef>

// ---------------------------------------------------------------------------
// MS-SSIM, 32x1x512x512 fp32 pairs, 5 levels, 11x11 Gaussian (sigma=1.5).
// SINGLE launch, interleaved scheduling (pyramid 1/5 of first 10240 blocks),
// (s,d) basis, packed f32x2, hbPQ aliased over sSD.
// Round 15: 8 blocks/SM (64 warps) + LDS.128 paired h-pass reads (SSTR=42,
// bank-perfect for 128-bit quarters).
// ---------------------------------------------------------------------------

#define TILE  32
#define HALO  5
#define SROWS (TILE + 2*HALO)   // 42
#define SSTR  42                // sSD row stride (u64) — bank-perfect for LDS.128
#define HSTR  33                // hb row stride (u64)
#define WIN   11

typedef unsigned long long u64;

#define GW0 0.00102839f
#define GW1 0.00759870f
#define GW2 0.03600080f
#define GW3 0.10936070f
#define GW4 0.21300540f
#define GW5 0.26601170f

#define C1F 1.0e-4f
#define C2F 9.0e-4f

#define OFF1 ((size_t)0)
#define OFF2 (OFF1 + (size_t)32 * 256 * 256)
#define OFF3 (OFF2 + (size_t)32 * 128 * 128)
#define OFF4 (OFF3 + (size_t)32 * 64 * 64)

#define N_PYR   2048
#define N_SSIM  10912
#define B_L1    10240
#define B_L2    12288
#define B_L3    12800
#define B_L4    12928
#define B_FIN   12960

__device__ float  g_buf1[32u * 87040u];
__device__ float  g_buf2[32u * 87040u];
__device__ double g_sums[10];
__device__ int    g_pyr1_done;
__device__ int    g_pyr_done;
__device__ int    g_done;

// ---- f32x2 packed helpers -------------------------------------------------
__device__ __forceinline__ void fma2(u64& d, u64 a, u64 b) {
    asm("fma.rn.f32x2 %0, %1, %2, %0;" : "+l"(d) : "l"(a), "l"(b));
}
__device__ __forceinline__ u64 mul2(u64 a, u64 b) {
    u64 r;
    asm("mul.rn.f32x2 %0, %1, %2;" : "=l"(r) : "l"(a), "l"(b));
    return r;
}
__device__ __forceinline__ u64 pack2(float x, float y) {
    u64 r;
    asm("mov.b64 %0, {%1, %2};" : "=l"(r) : "f"(x), "f"(y));
    return r;
}
__device__ __forceinline__ float lo32(u64 a) {
    float r;
    asm("{ .reg .f32 hi; mov.b64 {%0, hi}, %1; }" : "=f"(r) : "l"(a));
    return r;
}
__device__ __forceinline__ float hi32(u64 a) {
    float r;
    asm("{ .reg .f32 lo; mov.b64 {lo, %0}, %1; }" : "=f"(r) : "l"(a));
    return r;
}

// hbPQ aliases the sSD region (sSD dead after h-pass reads).
struct SsimSmem {
    union {
        u64 sSD[SROWS][SSTR];      // 14.1 KB
        u64 hbPQ[SROWS][HSTR];     // 11.1 KB
    };
    u64   hbSD[SROWS][HSTR];       // 11.1 KB
    float wsum[8][2];
};
struct PyrSmem {
    float a1[32][33], a2[32][33];
    float e1[16][17], e2[16][17];
    float c1[8][9],  c2[8][9];
};

__device__ __forceinline__ u64 wsel(int k) {
    const int kk = (k <= 5) ? k : (10 - k);
    switch (kk) {
        case 0:  return pack2(GW0, GW0);
        case 1:  return pack2(GW1, GW1);
        case 2:  return pack2(GW2, GW2);
        case 3:  return pack2(GW3, GW3);
        case 4:  return pack2(GW4, GW4);
        default: return pack2(GW5, GW5);
    }
}

// ---------------------------------------------------------------------------
__device__ __forceinline__ void ssim_body(
    int level, int H, int shift, int idx,
    const float* __restrict__ p1base, const float* __restrict__ p2base,
    SsimSmem& S, double* __restrict__ sums, int* __restrict__ done,
    int tx, int ty, int tid)
{
    const int nbx = 1 << shift;
    const int b   = idx >> (2 * shift);
    const int rem = idx & ((1 << (2 * shift)) - 1);
    const int byi = rem >> shift;
    const int bxi = rem & (nbx - 1);

    const int x0 = bxi * TILE - HALO;
    const int y0 = byi * TILE - HALO;

    const float* __restrict__ p1 = p1base + (size_t)b * H * H;
    const float* __restrict__ p2 = p2base + (size_t)b * H * H;

    // ---- load 42x42 halo tile as packed (u+v, u-v); zero pad = SAME ----
    const bool interior = (x0 >= 0) && (y0 >= 0) &&
                          (x0 + SROWS <= H) && (y0 + SROWS <= H);
    if (interior) {
#pragma unroll
        for (int rr = 0; rr < 6; rr++) {
            const int r = ty + 8 * rr;
            if (r < SROWS) {
                const size_t row = (size_t)(y0 + r) * H + x0;
#pragma unroll
                for (int cc = 0; cc < 2; cc++) {
                    const int c = tx + 32 * cc;
                    if (c < SROWS) {
                        const float u = p1[row + c];
                        const float v = p2[row + c];
                        S.sSD[r][c] = pack2(u + v, u - v);
                    }
                }
            }
        }
    } else {
#pragma unroll
        for (int rr = 0; rr < 6; rr++) {
            const int r = ty + 8 * rr;
            if (r < SROWS) {
                const int gy = y0 + r;
                const bool yok = (gy >= 0) && (gy < H);
#pragma unroll
                for (int cc = 0; cc < 2; cc++) {
                    const int c = tx + 32 * cc;
                    if (c < SROWS) {
                        const int gx = x0 + c;
                        float u = 0.f, v = 0.f;
                        if (yok && gx >= 0 && gx < H) {
                            u = p1[(size_t)gy * H + gx];
                            v = p2[(size_t)gy * H + gx];
                        }
                        S.sSD[r][c] = pack2(u + v, u - v);
                    }
                }
            }
        }
    }
    __syncthreads();

    // ---- horizontal pass (LDS.128 paired reads; PQ kept in regs) ----
    u64 APQ[4];
    int mr, mcg;
    {
        const int cg4  = tid & 3;
        const int rr   = tid >> 2;
        const int half = (rr >= 32) ? 1 : 0;
        mr  = rr - (half << 5);
        mcg = (cg4 + (half << 2)) << 2;
        const ulonglong2* __restrict__ srow2 =
            reinterpret_cast<const ulonglong2*>(&S.sSD[mr][mcg]);

        u64 ASD[4] = {0ull, 0ull, 0ull, 0ull};
        APQ[0] = APQ[1] = APQ[2] = APQ[3] = 0ull;
#pragma unroll
        for (int ii = 0; ii < 7; ii++) {
            const ulonglong2 pr = srow2[ii];      // one LDS.128 (conflict-free)
#pragma unroll
            for (int h = 0; h < 2; h++) {
                const int i  = 2 * ii + h;
                const u64 sd = h ? pr.y : pr.x;
                const u64 sq = mul2(sd, sd);
#pragma unroll
                for (int j = 0; j < 4; j++) {
                    const int k = i - j;
                    if (k >= 0 && k < WIN) {
                        fma2(ASD[j], wsel(k), sd);
                        fma2(APQ[j], wsel(k), sq);
                    }
                }
            }
        }
#pragma unroll
        for (int j = 0; j < 4; j++)
            S.hbSD[mr][mcg + j] = ASD[j];
    }
    // tail rows 32..41: 160 two-output subtasks; PQ kept in regs
    u64 T0PQ = 0ull, T1PQ = 0ull;
    int trr = 0, tc0 = 0;
    if (tid < 160) {
        const int G  = tid >> 4;
        const int L  = tid & 15;
        const int rp = G % 5;
        const int ch = G / 5;
        trr = 32 + 2 * rp + (L >> 3);
        const int sub = (L & 7) + 8 * ch;
        tc0 = sub << 1;
        const ulonglong2* __restrict__ srow2 =
            reinterpret_cast<const ulonglong2*>(&S.sSD[trr][tc0]);

        u64 A0SD = 0ull, A1SD = 0ull;
#pragma unroll
        for (int ii = 0; ii < 6; ii++) {
            const ulonglong2 pr = srow2[ii];      // one LDS.128
#pragma unroll
            for (int h = 0; h < 2; h++) {
                const int i  = 2 * ii + h;
                const u64 sd = h ? pr.y : pr.x;
                const u64 sq = mul2(sd, sd);
                if (i < 11) {
                    fma2(A0SD, wsel(i), sd);
                    fma2(T0PQ, wsel(i), sq);
                }
                if (i >= 1) {
                    fma2(A1SD, wsel(i - 1), sd);
                    fma2(T1PQ, wsel(i - 1), sq);
                }
            }
        }
        S.hbSD[trr][tc0]     = A0SD;
        S.hbSD[trr][tc0 + 1] = A1SD;
    }
    __syncthreads();   // all sSD reads complete -> safe to overwrite alias

    // ---- write PQ into the alias region ----
#pragma unroll
    for (int j = 0; j < 4; j++)
        S.hbPQ[mr][mcg + j] = APQ[j];
    if (tid < 160) {
        S.hbPQ[trr][tc0]     = T0PQ;
        S.hbPQ[trr][tc0 + 1] = T1PQ;
    }
    __syncthreads();

    // ---- vertical pass: thread = col tx, rows 4*ty .. 4*ty+3 ----
    u64 VSD[4] = {0ull, 0ull, 0ull, 0ull};
    u64 VPQ[4] = {0ull, 0ull, 0ull, 0ull};

    const int r0 = ty << 2;
#pragma unroll
    for (int i = 0; i < 14; i++) {
        const u64 hSD = S.hbSD[r0 + i][tx];
        const u64 hPQ = S.hbPQ[r0 + i][tx];
#pragma unroll
        for (int j = 0; j < 4; j++) {
            const int k = i - j;
            if (k >= 0 && k < WIN) {
                fma2(VSD[j], wsel(k), hSD);
                fma2(VPQ[j], wsel(k), hPQ);
            }
        }
    }

    float lssim = 0.f, lmcs = 0.f;
#pragma unroll
    for (int j = 0; j < 4; j++) {
        const float ms = lo32(VSD[j]);
        const float md = hi32(VSD[j]);
        const float P  = lo32(VPQ[j]);
        const float Q  = hi32(VPQ[j]);
        const float S2 = ms * ms;
        const float D2 = md * md;
        const float a  = 0.5f * (S2 - D2);
        const float bb = 0.5f * (S2 + D2);
        const float num2 = 0.5f * (P - Q) - a + C2F;
        const float den2 = 0.5f * (P + Q) - bb + C2F;
        const float mcs  = __fdividef(num2, den2);
        const float ssim = __fdividef(a + C1F, bb + C1F) * mcs;
        lssim += ssim;
        lmcs  += mcs;
    }

#pragma unroll
    for (int o = 16; o > 0; o >>= 1) {
        lssim += __shfl_down_sync(0xffffffffu, lssim, o);
        lmcs  += __shfl_down_sync(0xffffffffu, lmcs,  o);
    }
    if (tx == 0) {
        S.wsum[ty][0] = lssim;
        S.wsum[ty][1] = lmcs;
    }
    __syncthreads();
    if (ty == 0 && tx < 8) {
        float a = S.wsum[tx][0];
        float c = S.wsum[tx][1];
#pragma unroll
        for (int o = 4; o > 0; o >>= 1) {
            a += __shfl_down_sync(0xffu, a, o);
            c += __shfl_down_sync(0xffu, c, o);
        }
        if (tx == 0) {
            atomicAdd(&sums[2 * level + 0], (double)a);
            atomicAdd(&sums[2 * level + 1], (double)c);
            __threadfence();
            atomicAdd(done, 1);
        }
    }
}

// ---------------------------------------------------------------------------
__global__ __launch_bounds__(256, 8)
void mega_kernel(const float* __restrict__ img1,
                 const float* __restrict__ img2,
                 float* __restrict__ buf1,
                 float* __restrict__ buf2,
                 double* __restrict__ sums,
                 int* __restrict__ pyr1_done,
                 int* __restrict__ pyr_done,
                 int* __restrict__ done,
                 float* __restrict__ out)
{
    __shared__ __align__(16) unsigned char smraw[sizeof(SsimSmem)];

    const int tx  = threadIdx.x;
    const int ty  = threadIdx.y;
    const int tid = ty * 32 + tx;
    const int gb  = blockIdx.x;

    // ======================= finisher block ================================
    if (gb == B_FIN) {
        if (tid == 0) {
            volatile int* f = done;
            while (*f < N_SSIM) __nanosleep(256);
            __threadfence();

            const float w[5] = {0.0448f, 0.2856f, 0.3001f, 0.2363f, 0.1333f};
            float acc = 0.f;
#pragma unroll
            for (int l = 0; l < 4; l++) {
                const float N = 32.f * (float)(512 >> l) * (float)(512 >> l);
                const float mcs = (float)(sums[2 * l + 1] / (double)N);
                acc += w[l] * __log2f(mcs);
            }
            {
                const float N = 32.f * 32.f * 32.f;
                const float ssim = (float)(sums[2 * 4 + 0] / (double)N);
                acc += w[4] * __log2f(ssim);
            }
            out[0] = exp2f(acc);

#pragma unroll
            for (int i = 0; i < 10; i++) sums[i] = 0.0;
            __threadfence();
            *pyr1_done = 0;
            *pyr_done  = 0;
            *done      = 0;
        }
        return;
    }

    // ============ interleaved zone: pyramid (1/5) + level-0 (4/5) ==========
    if (gb < B_L1) {
        const int q  = gb / 5;
        const int rm = gb - 5 * q;

        if (rm == 0) {
            PyrSmem& P = *reinterpret_cast<PyrSmem*>(smraw);
            const int bx = q & 7, by = (q >> 3) & 7, b = q >> 6;

            const float* __restrict__ p1 = img1 + (size_t)b * 512 * 512;
            const float* __restrict__ p2 = img2 + (size_t)b * 512 * 512;

#pragma unroll
            for (int it = 0; it < 4; it++) {
                const int o  = tid + 256 * it;
                const int oy = o >> 5, ox = o & 31;
                const size_t r0 = (size_t)(by * 64 + 2 * oy) * 512 + bx * 64 + 2 * ox;
                const float2 u0 = *(const float2*)(p1 + r0);
                const float2 u1 = *(const float2*)(p1 + r0 + 512);
                const float2 v0 = *(const float2*)(p2 + r0);
                const float2 v1 = *(const float2*)(p2 + r0 + 512);
                const float d1 = 0.25f * (u0.x + u0.y + u1.x + u1.y);
                const float d2 = 0.25f * (v0.x + v0.y + v1.x + v1.y);
                P.a1[oy][ox] = d1;
                P.a2[oy][ox] = d2;
                const size_t gi = ((size_t)b * 256 + (by * 32 + oy)) * 256 + (bx * 32 + ox);
                buf1[OFF1 + gi] = d1;
                buf2[OFF1 + gi] = d2;
            }
            __threadfence();
            __syncthreads();
            if (tid == 0) atomicAdd(pyr1_done, 1);

            {
                const int oy = tid >> 4, ox = tid & 15;
                const float d1 = 0.25f * (P.a1[2*oy][2*ox] + P.a1[2*oy][2*ox+1] +
                                          P.a1[2*oy+1][2*ox] + P.a1[2*oy+1][2*ox+1]);
                const float d2 = 0.25f * (P.a2[2*oy][2*ox] + P.a2[2*oy][2*ox+1] +
                                          P.a2[2*oy+1][2*ox] + P.a2[2*oy+1][2*ox+1]);
                P.e1[oy][ox] = d1;
                P.e2[oy][ox] = d2;
                const size_t gi = ((size_t)b * 128 + (by * 16 + oy)) * 128 + (bx * 16 + ox);
                buf1[OFF2 + gi] = d1;
                buf2[OFF2 + gi] = d2;
            }
            __syncthreads();

            if (tid < 64) {
                const int oy = tid >> 3, ox = tid & 7;
                const float d1 = 0.25f * (P.e1[2*oy][2*ox] + P.e1[2*oy][2*ox+1] +
                                          P.e1[2*oy+1][2*ox] + P.e1[2*oy+1][2*ox+1]);
                const float d2 = 0.25f * (P.e2[2*oy][2*ox] + P.e2[2*oy][2*ox+1] +
                                          P.e2[2*oy+1][2*ox] + P.e2[2*oy+1][2*ox+1]);
                P.c1[oy][ox] = d1;
                P.c2[oy][ox] = d2;
                const size_t gi = ((size_t)b * 64 + (by * 8 + oy)) * 64 + (bx * 8 + ox);
                buf1[OFF3 + gi] = d1;
                buf2[OFF3 + gi] = d2;
            }
            __syncthreads();

            if (tid < 16) {
                const int oy = tid >> 2, ox = tid & 3;
                const float d1 = 0.25f * (P.c1[2*oy][2*ox] + P.c1[2*oy][2*ox+1] +
                                          P.c1[2*oy+1][2*ox] + P.c1[2*oy+1][2*ox+1]);
                const float d2 = 0.25f * (P.c2[2*oy][2*ox] + P.c2[2*oy][2*ox+1] +
                                          P.c2[2*oy+1][2*ox] + P.c2[2*oy+1][2*ox+1]);
                const size_t gi = ((size_t)b * 32 + (by * 4 + oy)) * 32 + (bx * 4 + ox);
                buf1[OFF4 + gi] = d1;
                buf2[OFF4 + gi] = d2;
            }
            __threadfence();
            __syncthreads();
            if (tid == 0) atomicAdd(pyr_done, 1);
            return;
        }

        SsimSmem& S = *reinterpret_cast<SsimSmem*>(smraw);
        const int idx = q * 4 + (rm - 1);
        ssim_body(0, 512, 4, idx, img1, img2, S, sums, done, tx, ty, tid);
        return;
    }

    // ======================= levels 1..4 ===================================
    SsimSmem& S = *reinterpret_cast<SsimSmem*>(smraw);

    int level, start;
    const float *p1base, *p2base;
    if (gb < B_L2)      { level = 1; start = B_L1; p1base = buf1 + OFF1; p2base = buf2 + OFF1; }
    else if (gb < B_L3) { level = 2; start = B_L2; p1base = buf1 + OFF2; p2base = buf2 + OFF2; }
    else if (gb < B_L4) { level = 3; start = B_L3; p1base = buf1 + OFF3; p2base = buf2 + OFF3; }
    else                { level = 4; start = B_L4; p1base = buf1 + OFF4; p2base = buf2 + OFF4; }

    if (level == 1) {
        if (tid == 0) {
            volatile int* f = pyr1_done;
            while (*f < N_PYR) __nanosleep(128);
            __threadfence();
        }
        __syncthreads();
    } else {
        if (tid == 0) {
            volatile int* f = pyr_done;
            while (*f < N_PYR) __nanosleep(128);
            __threadfence();
        }
        __syncthreads();
    }

    const int shift = 4 - level;
    const int H     = 512 >> level;
    const int idx   = gb - start;
    ssim_body(level, H, shift, idx, p1base, p2base, S, sums, done, tx, ty, tid);
}

extern "C" void kernel_launch(void* const* d_in, const int* in_sizes, int n_in,
                              void* d_out, int out_size)
{
    const float* img1 = (const float*)d_in[0];
    const float* img2 = (const float*)d_in[1];
    float* out = (float*)d_out;

    double* sums = nullptr;
    float*  buf1 = nullptr;
    float*  buf2 = nullptr;
    int *f1 = nullptr, *f2 = nullptr, *f3 = nullptr;
    cudaGetSymbolAddress((void**)&sums, g_sums);
    cudaGetSymbolAddress((void**)&buf1, g_buf1);
    cudaGetSymbolAddress((void**)&buf2, g_buf2);
    cudaGetSymbolAddress((void**)&f1, g_pyr1_done);
    cudaGetSymbolAddress((void**)&f2, g_pyr_done);
    cudaGetSymbolAddress((void**)&f3, g_done);

    mega_kernel<<<B_FIN + 1, dim3(32, 8)>>>(img1, img2, buf1, buf2,
                                            sums, f1, f2, f3, out);
}